// round 14
// baseline (speedup 1.0000x reference)
#include <cuda_runtime.h>
#include <cstdint>

#define NN 128
#define LFULL 1024
#define CC 512
#define KTOT 2045
#define L1S 1023
#define L2S 1022

static __device__ __constant__ float INV_T = 14.2857142857142857f; // 1/0.07

// ---------------- device scratch (allocation-free rule) ----------------
// Pair-permuted layout within each 8-float k-group (R11-proven):
//   position 2t   holds original k = t
//   position 2t+1 holds original k = t+4      (t = 0..3)
__device__ float g_T[(size_t)NN * LFULL * CC];   // 268 MB: tf32-rounded + pair-permuted
__device__ float g_P[(size_t)NN * LFULL * CC];   // 268 MB: tf32-rounded + pair-permuted
__device__ float g_U[(size_t)NN * L1S * CC];     // 268 MB: U = T@W, rounded + pair-permuted
__device__ float g_Wt[CC * CC];                  // W^T, rounded + pair-permuted
__device__ float g_tb[L1S * NN];                 // tb[l][n]
__device__ float g_tmp[(size_t)L1S * NN * NN];   // 67 MB: [l][n][m] (already /T)
__device__ unsigned int g_cnt[2];

// ---------------- helpers ----------------
__device__ __forceinline__ float tf32r(float x) {
    unsigned r;
    asm("cvt.rna.tf32.f32 %0, %1;" : "=r"(r) : "f"(x));
    return __uint_as_float(r);
}
__device__ __forceinline__ void cp16(unsigned s, const void* g) {
    asm volatile("cp.async.cg.shared.global [%0], [%1], 16;" :: "r"(s), "l"(g));
}
#define CP_COMMIT() asm volatile("cp.async.commit_group;" ::: "memory")
#define CP_WAIT(n)  asm volatile("cp.async.wait_group %0;" :: "n"(n) : "memory")

// D += A*B : m16n8k8 tf32 (A row-major, B col-major), fp32 accum
__device__ __forceinline__ void mma1688(float* c, const unsigned* a, const unsigned* b) {
    asm volatile(
        "mma.sync.aligned.m16n8k8.row.col.f32.tf32.tf32.f32 "
        "{%0,%1,%2,%3}, {%4,%5,%6,%7}, {%8,%9}, {%0,%1,%2,%3};"
        : "+f"(c[0]), "+f"(c[1]), "+f"(c[2]), "+f"(c[3])
        : "r"(a[0]), "r"(a[1]), "r"(a[2]), "r"(a[3]), "r"(b[0]), "r"(b[1]));
}

// smem tile: 128 rows x 32 k (pair-permuted), pitch 36 floats (144B)
#define KS 32
#define ROWB 144
#define TILE_B (128 * ROWB)            // 18432 bytes
#define OFF_A(buf) ((buf) * 2 * TILE_B)
#define OFF_B(buf) (OFF_A(buf) + TILE_B)
#define SM_GEMM (6 * TILE_B)           // 110592 (3-stage ring)
#define SM_TOTAL (SM_GEMM + 512)
#define SPAD 132

// ======================= misc kernels =======================
__global__ void init_kernel() { g_cnt[0] = 0u; g_cnt[1] = 0u; }

// one 32-float group per thread: tf32-round + pair-permute each 8-group.
// dst positions {0..7} <- src k {0,4,1,5,2,6,3,7}  (== R11 sts_perm layout).
// NOTE: dst is a __device__ global referenced INSIDE device code (host code
// must never pass device symbols as kernel args — that was the R12/R13 bug).
__device__ __forceinline__ void prep_body(const float* __restrict__ src,
                                          float* __restrict__ dst) {
    size_t g = (size_t)blockIdx.x * 256 + threadIdx.x;
    const float4* s4 = (const float4*)(src + g * 32);
    float in[32];
#pragma unroll
    for (int q = 0; q < 8; q++) {
        float4 v = s4[q];
        in[q * 4 + 0] = v.x; in[q * 4 + 1] = v.y;
        in[q * 4 + 2] = v.z; in[q * 4 + 3] = v.w;
    }
    float4* d4 = (float4*)(dst + g * 32);
#pragma unroll
    for (int q = 0; q < 8; q++) {
        int g8 = (q >> 1) * 8;          // which 8-group
        int po = (q & 1) * 4;           // position offset within group
        float4 o;
        o.x = tf32r(in[g8 + ((po + 0) >> 1) + ((po + 0) & 1) * 4]);
        o.y = tf32r(in[g8 + ((po + 1) >> 1) + ((po + 1) & 1) * 4]);
        o.z = tf32r(in[g8 + ((po + 2) >> 1) + ((po + 2) & 1) * 4]);
        o.w = tf32r(in[g8 + ((po + 3) >> 1) + ((po + 3) & 1) * 4]);
        d4[q] = o;
    }
}
__global__ void prepT_kernel(const float* __restrict__ src) { prep_body(src, g_T); }
__global__ void prepP_kernel(const float* __restrict__ src) { prep_body(src, g_P); }

__global__ void tb_kernel(const float* __restrict__ t, const float* __restrict__ b,
                          int Lp, int step) {
    int l = blockIdx.x, n = threadIdx.x;
    const float4* r4 = (const float4*)(t + ((size_t)n * LFULL + l + step) * CC);
    const float4* b4 = (const float4*)b;
    float s = 0.f;
#pragma unroll 8
    for (int i = 0; i < CC / 4; i++) {
        float4 a = r4[i], bb = b4[i];
        s += a.x * bb.x + a.y * bb.y + a.z * bb.z + a.w * bb.w;
    }
    g_tb[l * NN + n] = s;
}

// g_Wt[p][pair-perm(c)] = tf32_round(W[c][p])   (byte-identical to R11)
__global__ void wt_kernel(const float* __restrict__ W) {
    __shared__ float t[32][33];
    int c0 = blockIdx.y * 32, p0 = blockIdx.x * 32;
    int tx = threadIdx.x, ty = threadIdx.y;
#pragma unroll
    for (int i = 0; i < 4; i++)
        t[ty + 8 * i][tx] = W[(size_t)(c0 + ty + 8 * i) * CC + p0 + tx];
    __syncthreads();
    int cp_ = (tx & ~7) | (((tx & 3) << 1) | ((tx >> 2) & 1));
#pragma unroll
    for (int i = 0; i < 4; i++)
        g_Wt[(size_t)(p0 + ty + 8 * i) * CC + c0 + cp_] = tf32r(t[tx][ty + 8 * i]);
}

__global__ void transpose_kernel(float* __restrict__ out, int Lp, int kbase) {
    __shared__ float tile[32][33];
    int n = blockIdx.z;
    int l0 = blockIdx.x * 32, m0 = blockIdx.y * 32;
    int tx = threadIdx.x, ty = threadIdx.y;
#pragma unroll
    for (int i = 0; i < 4; i++) {
        int l = l0 + ty + i * 8;
        if (l < Lp) tile[ty + i * 8][tx] = g_tmp[((size_t)l * NN + n) * NN + m0 + tx];
    }
    __syncthreads();
#pragma unroll
    for (int i = 0; i < 4; i++) {
        int m = m0 + ty + i * 8;
        int l = l0 + tx;
        if (l < Lp) out[((size_t)n * NN + m) * KTOT + kbase + l] = tile[tx][ty + i * 8];
    }
}

__global__ void ytrue_kernel(float* __restrict__ out) {
    int idx = blockIdx.x * 256 + threadIdx.x;
    if (idx < NN * KTOT) out[(size_t)NN * NN * KTOT + idx] = (float)(idx / KTOT);
}

__global__ void acc_kernel(float* __restrict__ out) {
    size_t off = (size_t)NN * NN * KTOT + (size_t)NN * KTOT;
    out[off + 0] = (float)g_cnt[0] / (float)(NN * L1S);
    out[off + 1] = (float)g_cnt[1] / (float)(NN * L2S);
}

// ============ warp microkernel (byte-identical to R11): 8 warps, 32x64 tiles ============
__device__ __forceinline__ void compute_half(const char* sm, int buf, int h,
                                             int wr, int wc, int gid, int tig,
                                             float acc[2][8][4]) {
    const char* Ab = sm + OFF_A(buf);
    const char* Bb = sm + OFF_B(buf);
#pragma unroll
    for (int k8 = h * 2; k8 < h * 2 + 2; k8++) {
        uint2 afl[2], afh[2];
#pragma unroll
        for (int mi = 0; mi < 2; mi++) {
            int r = wr * 32 + mi * 16 + gid;
            afl[mi] = *(const uint2*)(Ab + r * ROWB + k8 * 32 + tig * 8);
            afh[mi] = *(const uint2*)(Ab + (r + 8) * ROWB + k8 * 32 + tig * 8);
        }
        uint2 bf2[8];
#pragma unroll
        for (int ni = 0; ni < 8; ni++) {
            int c = wc * 64 + ni * 8 + gid;
            bf2[ni] = *(const uint2*)(Bb + c * ROWB + k8 * 32 + tig * 8);
        }
#pragma unroll
        for (int mi = 0; mi < 2; mi++) {
            unsigned a[4] = {afl[mi].x, afh[mi].x, afl[mi].y, afh[mi].y};
#pragma unroll
            for (int ni = 0; ni < 8; ni++) {
                unsigned b[2] = {bf2[ni].x, bf2[ni].y};
                mma1688(acc[mi][ni], a, b);
            }
        }
    }
}

// ======================= gemmU: U = T @ Wt^T (pure cp.async) =======================
__global__ void __launch_bounds__(256, 2)
gemmU_mma(int Lp, int step) {
    extern __shared__ char sm[];
    unsigned sb = (unsigned)__cvta_generic_to_shared(sm);
    int tid = threadIdx.x, wid = tid >> 5, lid = tid & 31;
    int wr = wid & 3, wc = wid >> 2, gid = lid >> 2, tig = lid & 3;
    int colbase = blockIdx.x * 128;
    int r0 = blockIdx.y * 128;

    unsigned* rows = (unsigned*)(sm + SM_GEMM);
    if (tid < 128) {
        int r = r0 + tid;
        int n = r / Lp, l = r - n * Lp;
        rows[tid] = (unsigned)((n * LFULL + l + step) * CC);
    }
    __syncthreads();

    int crow = tid >> 3, cc4 = tid & 7;
    unsigned rbase[4], wbase[4];
#pragma unroll
    for (int j = 0; j < 4; j++) {
        rbase[j] = rows[crow + j * 32];
        wbase[j] = (unsigned)(colbase + crow + j * 32) * CC;
    }

    // prologue: stages 0,1
#pragma unroll
    for (int ps = 0; ps < 2; ps++) {
        int kt = ps * KS;
        unsigned ab = sb + OFF_A(ps), bb = sb + OFF_B(ps);
#pragma unroll
        for (int j = 0; j < 4; j++) {
            int row = crow + j * 32;
            cp16(ab + row * ROWB + cc4 * 16, g_T + rbase[j] + kt + cc4 * 4);
            cp16(bb + row * ROWB + cc4 * 16, g_Wt + wbase[j] + kt + cc4 * 4);
        }
        CP_COMMIT();
    }

    float acc[2][8][4] = {};
#pragma unroll 1
    for (int s = 0; s < 16; s++) {
        if (s < 15) CP_WAIT(1); else CP_WAIT(0);
        __syncthreads();
        if (s + 2 < 16) {
            int kt = (s + 2) * KS;
            int nb = (s + 2) % 3;
            unsigned ab = sb + OFF_A(nb), bb = sb + OFF_B(nb);
#pragma unroll
            for (int j = 0; j < 4; j++) {
                int row = crow + j * 32;
                cp16(ab + row * ROWB + cc4 * 16, g_T + rbase[j] + kt + cc4 * 4);
                cp16(bb + row * ROWB + cc4 * 16, g_Wt + wbase[j] + kt + cc4 * 4);
            }
            CP_COMMIT();
        }
        int buf = s % 3;
        compute_half(sm, buf, 0, wr, wc, gid, tig, acc);
        compute_half(sm, buf, 1, wr, wc, gid, tig, acc);
    }

    // epilogue: store tf32-rounded U in pair-permuted layout (R11-proven perm)
    int p0 = ((2 * tig) & 3) * 2 + ((tig >> 1) & 1);   // perm(2*tig)
    int p1 = p0 + 2;                                    // perm(2*tig+1)
#pragma unroll
    for (int mi = 0; mi < 2; mi++) {
        int rA = r0 + wr * 32 + mi * 16 + gid;
#pragma unroll
        for (int ni = 0; ni < 8; ni++) {
            int base8 = colbase + wc * 64 + ni * 8;
            float* u0 = g_U + (size_t)rA * CC + base8;
            float* u1 = g_U + (size_t)(rA + 8) * CC + base8;
            u0[p0] = tf32r(acc[mi][ni][0]);
            u0[p1] = tf32r(acc[mi][ni][1]);
            u1[p0] = tf32r(acc[mi][ni][2]);
            u1[p1] = tf32r(acc[mi][ni][3]);
        }
    }
}

// ======================= gemmL: per-l 128x128x512 Gram (pure cp.async) =======================
__global__ void __launch_bounds__(256, 2)
gemmL_mma(int Lp, int stepIdx) {
    extern __shared__ char sm[];
    unsigned sb = (unsigned)__cvta_generic_to_shared(sm);
    int tid = threadIdx.x, wid = tid >> 5, lid = tid & 31;
    int wr = wid & 3, wc = wid >> 2, gid = lid >> 2, tig = lid & 3;
    int l = blockIdx.x;

    int crow = tid >> 3, cc4 = tid & 7;
    unsigned abase[4], bbase[4];
#pragma unroll
    for (int j = 0; j < 4; j++) {
        int row = crow + j * 32;
        abase[j] = (unsigned)(row * Lp + l) * CC;
        bbase[j] = (unsigned)(row * LFULL + l) * CC;
    }

    // prologue: stages 0,1
#pragma unroll
    for (int ps = 0; ps < 2; ps++) {
        int kt = ps * KS;
        unsigned ab = sb + OFF_A(ps), bb = sb + OFF_B(ps);
#pragma unroll
        for (int j = 0; j < 4; j++) {
            int row = crow + j * 32;
            cp16(ab + row * ROWB + cc4 * 16, g_U + abase[j] + kt + cc4 * 4);
            cp16(bb + row * ROWB + cc4 * 16, g_P + bbase[j] + kt + cc4 * 4);
        }
        CP_COMMIT();
    }

    float acc[2][8][4] = {};
#pragma unroll 1
    for (int s = 0; s < 16; s++) {
        if (s < 15) CP_WAIT(1); else CP_WAIT(0);
        __syncthreads();
        if (s + 2 < 16) {
            int kt = (s + 2) * KS;
            int nb = (s + 2) % 3;
            unsigned ab = sb + OFF_A(nb), bb = sb + OFF_B(nb);
#pragma unroll
            for (int j = 0; j < 4; j++) {
                int row = crow + j * 32;
                cp16(ab + row * ROWB + cc4 * 16, g_U + abase[j] + kt + cc4 * 4);
                cp16(bb + row * ROWB + cc4 * 16, g_P + bbase[j] + kt + cc4 * 4);
            }
            CP_COMMIT();
        }
        int buf = s % 3;
        compute_half(sm, buf, 0, wr, wc, gid, tig, acc);
        compute_half(sm, buf, 1, wr, wc, gid, tig, acc);
    }
    __syncthreads();   // all compute done before S overwrites buffer 0

    // epilogue: S[n][m] = (acc + tb[n]) * INV_T
    float* S = (float*)sm;
#pragma unroll
    for (int mi = 0; mi < 2; mi++) {
        int n0 = wr * 32 + mi * 16 + gid;
        float tbl = g_tb[l * NN + n0];
        float tbh = g_tb[l * NN + n0 + 8];
#pragma unroll
        for (int ni = 0; ni < 8; ni++) {
            int col = wc * 64 + ni * 8 + 2 * tig;
            S[n0 * SPAD + col]           = (acc[mi][ni][0] + tbl) * INV_T;
            S[n0 * SPAD + col + 1]       = (acc[mi][ni][1] + tbl) * INV_T;
            S[(n0 + 8) * SPAD + col]     = (acc[mi][ni][2] + tbh) * INV_T;
            S[(n0 + 8) * SPAD + col + 1] = (acc[mi][ni][3] + tbh) * INV_T;
        }
    }
    __syncthreads();

    // NCE accuracy (INV_T > 0 preserves ordering)
    if (tid < 128) {
        float pos = S[tid * SPAD + tid];
        bool ok = true;
#pragma unroll 8
        for (int m = 0; m < NN; m++)
            ok = ok && ((m == tid) || (pos > S[tid * SPAD + m]));
        unsigned msk = __ballot_sync(0xffffffffu, ok);
        if (lid == 0) atomicAdd(&g_cnt[stepIdx], (unsigned)__popc(msk));
    }
    // coalesced staged store: S[n][m] -> g_tmp[l][n][m]
    for (int idx = tid; idx < NN * NN / 4; idx += 256) {
        int n2 = idx >> 5, m4 = (idx & 31) * 4;
        float4 v = *(float4*)&S[n2 * SPAD + m4];
        *(float4*)&g_tmp[((size_t)l * NN + n2) * NN + m4] = v;
    }
}

// ======================= launch =======================
extern "C" void kernel_launch(void* const* d_in, const int* in_sizes, int n_in,
                              void* d_out, int out_size) {
    const float* ts  = (const float*)d_in[0];
    const float* pts = (const float*)d_in[1];
    const float* W1  = (const float*)d_in[2];
    const float* b1  = (const float*)d_in[3];
    const float* W2  = (const float*)d_in[4];
    const float* b2  = (const float*)d_in[5];
    float* out = (float*)d_out;

    static bool attr_done = false;
    if (!attr_done) {
        cudaFuncSetAttribute(gemmU_mma, cudaFuncAttributeMaxDynamicSharedMemorySize, SM_TOTAL);
        cudaFuncSetAttribute(gemmL_mma, cudaFuncAttributeMaxDynamicSharedMemorySize, SM_TOTAL);
        attr_done = true;
    }

    init_kernel<<<1, 1>>>();
    // one-time: rounded + pair-permuted copies of T and P (reused by both steps)
    prepT_kernel<<<(NN * LFULL * CC / 32) / 256, 256>>>(ts);
    prepP_kernel<<<(NN * LFULL * CC / 32) / 256, 256>>>(pts);

    const float* Ws[2] = {W1, W2};
    const float* bs[2] = {b1, b2};
    int kb = 0;
    for (int si = 0; si < 2; si++) {
        int step = si + 1;
        int Lp = LFULL - step;
        wt_kernel<<<dim3(16, 16), dim3(32, 8)>>>(Ws[si]);
        tb_kernel<<<Lp, 128>>>(ts, bs[si], Lp, step);
        gemmU_mma<<<dim3(4, Lp), 256, SM_TOTAL>>>(Lp, step);
        gemmL_mma<<<Lp, 256, SM_TOTAL>>>(Lp, si);
        transpose_kernel<<<dim3(32, 4, 128), dim3(32, 8)>>>(out, Lp, kb);
        kb += Lp;
    }
    ytrue_kernel<<<(NN * KTOT + 255) / 256, 256>>>(out);
    acc_kernel<<<1, 1>>>(out);
}

// round 16
// speedup vs baseline: 1.1152x; 1.1152x over previous
#include <cuda_runtime.h>
#include <cstdint>

#define NN 128
#define LFULL 1024
#define CC 512
#define KTOT 2045
#define L1S 1023
#define L2S 1022

static __device__ __constant__ float INV_T = 14.2857142857142857f; // 1/0.07

// ---------------- device scratch (allocation-free rule) ----------------
// Pair-permuted layout within each 8-float k-group (R11-proven):
//   position 2t   holds original k = t
//   position 2t+1 holds original k = t+4      (t = 0..3)
__device__ float g_T[(size_t)NN * LFULL * CC];   // 268 MB: tf32-rounded + pair-permuted
__device__ float g_P[(size_t)NN * LFULL * CC];   // 268 MB: tf32-rounded + pair-permuted
__device__ float g_U[(size_t)NN * L1S * CC];     // 268 MB: U = T@W, rounded + pair-permuted
__device__ float g_Wt[CC * CC];                  // W^T, rounded + pair-permuted
__device__ float g_tb[L1S * NN];                 // tb[l][n]
__device__ float g_tmp[(size_t)L1S * NN * NN];   // 67 MB: [l][n][m] (already /T)
__device__ unsigned int g_cnt[2];

// ---------------- helpers ----------------
__device__ __forceinline__ float tf32r(float x) {
    unsigned r;
    asm("cvt.rna.tf32.f32 %0, %1;" : "=r"(r) : "f"(x));
    return __uint_as_float(r);
}
__device__ __forceinline__ void cp16(unsigned s, const void* g) {
    asm volatile("cp.async.cg.shared.global [%0], [%1], 16;" :: "r"(s), "l"(g));
}
#define CP_COMMIT() asm volatile("cp.async.commit_group;" ::: "memory")
#define CP_WAIT(n)  asm volatile("cp.async.wait_group %0;" :: "n"(n) : "memory")

// D += A*B : m16n8k8 tf32 (A row-major, B col-major), fp32 accum
__device__ __forceinline__ void mma1688(float* c, const unsigned* a, const unsigned* b) {
    asm volatile(
        "mma.sync.aligned.m16n8k8.row.col.f32.tf32.tf32.f32 "
        "{%0,%1,%2,%3}, {%4,%5,%6,%7}, {%8,%9}, {%0,%1,%2,%3};"
        : "+f"(c[0]), "+f"(c[1]), "+f"(c[2]), "+f"(c[3])
        : "r"(a[0]), "r"(a[1]), "r"(a[2]), "r"(a[3]), "r"(b[0]), "r"(b[1]));
}

// smem tile: 128 rows x 32 k (pair-permuted), pitch 128B, XOR chunk swizzle:
//   16B chunk c of row r lives at chunk position  c ^ ((r & 3) << 1)
// Conflict-free for both the LDS.64 fragment pattern and cp.async stores.
#define KS 32
#define ROWB 128
#define TILE_B (128 * ROWB)            // 16384 bytes
#define OFF_A(buf) ((buf) * 2 * TILE_B)
#define OFF_B(buf) (OFF_A(buf) + TILE_B)
#define SM_GEMM (6 * TILE_B)           // 98304 (3-stage ring)
#define SM_TOTAL (SM_GEMM + 512)
#define SPAD 132

// ======================= misc kernels =======================
__global__ void init_kernel() { g_cnt[0] = 0u; g_cnt[1] = 0u; }

// one 32-float group per thread: tf32-round + pair-permute each 8-group.
// dst positions {0..7} <- src k {0,4,1,5,2,6,3,7}  (== R11 sts_perm layout).
// NOTE: dst must be referenced INSIDE device code (device-symbol-as-host-arg
// was the R12/R13 bug).
__device__ __forceinline__ void prep_body(const float* __restrict__ src,
                                          float* __restrict__ dst) {
    size_t g = (size_t)blockIdx.x * 256 + threadIdx.x;
    const float4* s4 = (const float4*)(src + g * 32);
    float in[32];
#pragma unroll
    for (int q = 0; q < 8; q++) {
        float4 v = s4[q];
        in[q * 4 + 0] = v.x; in[q * 4 + 1] = v.y;
        in[q * 4 + 2] = v.z; in[q * 4 + 3] = v.w;
    }
    float4* d4 = (float4*)(dst + g * 32);
#pragma unroll
    for (int q = 0; q < 8; q++) {
        int g8 = (q >> 1) * 8;          // which 8-group
        int po = (q & 1) * 4;           // position offset within group
        float4 o;
        o.x = tf32r(in[g8 + ((po + 0) >> 1) + ((po + 0) & 1) * 4]);
        o.y = tf32r(in[g8 + ((po + 1) >> 1) + ((po + 1) & 1) * 4]);
        o.z = tf32r(in[g8 + ((po + 2) >> 1) + ((po + 2) & 1) * 4]);
        o.w = tf32r(in[g8 + ((po + 3) >> 1) + ((po + 3) & 1) * 4]);
        d4[q] = o;
    }
}
__global__ void prepT_kernel(const float* __restrict__ src) { prep_body(src, g_T); }
__global__ void prepP_kernel(const float* __restrict__ src) { prep_body(src, g_P); }

__global__ void tb_kernel(const float* __restrict__ t, const float* __restrict__ b,
                          int Lp, int step) {
    int l = blockIdx.x, n = threadIdx.x;
    const float4* r4 = (const float4*)(t + ((size_t)n * LFULL + l + step) * CC);
    const float4* b4 = (const float4*)b;
    float s = 0.f;
#pragma unroll 8
    for (int i = 0; i < CC / 4; i++) {
        float4 a = r4[i], bb = b4[i];
        s += a.x * bb.x + a.y * bb.y + a.z * bb.z + a.w * bb.w;
    }
    g_tb[l * NN + n] = s;
}

// g_Wt[p][pair-perm(c)] = tf32_round(W[c][p])
__global__ void wt_kernel(const float* __restrict__ W) {
    __shared__ float t[32][33];
    int c0 = blockIdx.y * 32, p0 = blockIdx.x * 32;
    int tx = threadIdx.x, ty = threadIdx.y;
#pragma unroll
    for (int i = 0; i < 4; i++)
        t[ty + 8 * i][tx] = W[(size_t)(c0 + ty + 8 * i) * CC + p0 + tx];
    __syncthreads();
    int cp_ = (tx & ~7) | (((tx & 3) << 1) | ((tx >> 2) & 1));
#pragma unroll
    for (int i = 0; i < 4; i++)
        g_Wt[(size_t)(p0 + ty + 8 * i) * CC + c0 + cp_] = tf32r(t[tx][ty + 8 * i]);
}

__global__ void transpose_kernel(float* __restrict__ out, int Lp, int kbase) {
    __shared__ float tile[32][33];
    int n = blockIdx.z;
    int l0 = blockIdx.x * 32, m0 = blockIdx.y * 32;
    int tx = threadIdx.x, ty = threadIdx.y;
#pragma unroll
    for (int i = 0; i < 4; i++) {
        int l = l0 + ty + i * 8;
        if (l < Lp) tile[ty + i * 8][tx] = g_tmp[((size_t)l * NN + n) * NN + m0 + tx];
    }
    __syncthreads();
#pragma unroll
    for (int i = 0; i < 4; i++) {
        int m = m0 + ty + i * 8;
        int l = l0 + tx;
        if (l < Lp) out[((size_t)n * NN + m) * KTOT + kbase + l] = tile[tx][ty + i * 8];
    }
}

__global__ void ytrue_kernel(float* __restrict__ out) {
    int idx = blockIdx.x * 256 + threadIdx.x;
    if (idx < NN * KTOT) out[(size_t)NN * NN * KTOT + idx] = (float)(idx / KTOT);
}

__global__ void acc_kernel(float* __restrict__ out) {
    size_t off = (size_t)NN * NN * KTOT + (size_t)NN * KTOT;
    out[off + 0] = (float)g_cnt[0] / (float)(NN * L1S);
    out[off + 1] = (float)g_cnt[1] / (float)(NN * L2S);
}

// ============ warp microkernel: 8 warps, 32x64 tiles, swizzled LDS.64 ============
// fragment chunk = k8*2 + (tig>>1); swizzle XOR = (r&3)<<1 == (gid&3)<<1 for
// every A/B row this thread touches (all row offsets are multiples of 4).
__device__ __forceinline__ void compute_half(const char* sm, int buf, int h,
                                             int wr, int wc, int gid, int tig,
                                             float acc[2][8][4]) {
    const char* Ab = sm + OFF_A(buf);
    const char* Bb = sm + OFF_B(buf);
    int sw = (gid & 3) << 1;
    int h8 = (tig & 1) * 8;
    int th = tig >> 1;
#pragma unroll
    for (int k8 = h * 2; k8 < h * 2 + 2; k8++) {
        int coff = (((k8 * 2 + th) ^ sw) << 4) + h8;
        uint2 afl[2], afh[2];
#pragma unroll
        for (int mi = 0; mi < 2; mi++) {
            int r = wr * 32 + mi * 16 + gid;
            afl[mi] = *(const uint2*)(Ab + r * ROWB + coff);
            afh[mi] = *(const uint2*)(Ab + (r + 8) * ROWB + coff);
        }
        uint2 bf2[8];
#pragma unroll
        for (int ni = 0; ni < 8; ni++) {
            int c = wc * 64 + ni * 8 + gid;
            bf2[ni] = *(const uint2*)(Bb + c * ROWB + coff);
        }
#pragma unroll
        for (int mi = 0; mi < 2; mi++) {
            unsigned a[4] = {afl[mi].x, afh[mi].x, afl[mi].y, afh[mi].y};
#pragma unroll
            for (int ni = 0; ni < 8; ni++) {
                unsigned b[2] = {bf2[ni].x, bf2[ni].y};
                mma1688(acc[mi][ni], a, b);
            }
        }
    }
}

// ======================= gemmU: U = T @ Wt^T (pure cp.async) =======================
__global__ void __launch_bounds__(256, 2)
gemmU_mma(int Lp, int step) {
    extern __shared__ char sm[];
    unsigned sb = (unsigned)__cvta_generic_to_shared(sm);
    int tid = threadIdx.x, wid = tid >> 5, lid = tid & 31;
    int wr = wid & 3, wc = wid >> 2, gid = lid >> 2, tig = lid & 3;
    int colbase = blockIdx.x * 128;
    int r0 = blockIdx.y * 128;

    unsigned* rows = (unsigned*)(sm + SM_GEMM);
    if (tid < 128) {
        int r = r0 + tid;
        int n = r / Lp, l = r - n * Lp;
        rows[tid] = (unsigned)((n * LFULL + l + step) * CC);
    }
    __syncthreads();

    int crow = tid >> 3, cc4 = tid & 7;
    int cpos = ((cc4 ^ ((crow & 3) << 1)) << 4);   // swizzled chunk byte offset
    unsigned rbase[4], wbase[4];
#pragma unroll
    for (int j = 0; j < 4; j++) {
        rbase[j] = rows[crow + j * 32];
        wbase[j] = (unsigned)(colbase + crow + j * 32) * CC;
    }

    // prologue: stages 0,1
#pragma unroll
    for (int ps = 0; ps < 2; ps++) {
        int kt = ps * KS;
        unsigned ab = sb + OFF_A(ps), bb = sb + OFF_B(ps);
#pragma unroll
        for (int j = 0; j < 4; j++) {
            int row = crow + j * 32;
            cp16(ab + row * ROWB + cpos, g_T + rbase[j] + kt + cc4 * 4);
            cp16(bb + row * ROWB + cpos, g_Wt + wbase[j] + kt + cc4 * 4);
        }
        CP_COMMIT();
    }

    float acc[2][8][4] = {};
#pragma unroll 1
    for (int s = 0; s < 16; s++) {
        if (s < 15) CP_WAIT(1); else CP_WAIT(0);
        __syncthreads();
        if (s + 2 < 16) {
            int kt = (s + 2) * KS;
            int nb = (s + 2) % 3;
            unsigned ab = sb + OFF_A(nb), bb = sb + OFF_B(nb);
#pragma unroll
            for (int j = 0; j < 4; j++) {
                int row = crow + j * 32;
                cp16(ab + row * ROWB + cpos, g_T + rbase[j] + kt + cc4 * 4);
                cp16(bb + row * ROWB + cpos, g_Wt + wbase[j] + kt + cc4 * 4);
            }
            CP_COMMIT();
        }
        int buf = s % 3;
        compute_half(sm, buf, 0, wr, wc, gid, tig, acc);
        compute_half(sm, buf, 1, wr, wc, gid, tig, acc);
    }

    // epilogue: store tf32-rounded U in pair-permuted layout (R11-proven perm)
    int p0 = ((2 * tig) & 3) * 2 + ((tig >> 1) & 1);   // perm(2*tig)
    int p1 = p0 + 2;                                    // perm(2*tig+1)
#pragma unroll
    for (int mi = 0; mi < 2; mi++) {
        int rA = r0 + wr * 32 + mi * 16 + gid;
#pragma unroll
        for (int ni = 0; ni < 8; ni++) {
            int base8 = colbase + wc * 64 + ni * 8;
            float* u0 = g_U + (size_t)rA * CC + base8;
            float* u1 = g_U + (size_t)(rA + 8) * CC + base8;
            u0[p0] = tf32r(acc[mi][ni][0]);
            u0[p1] = tf32r(acc[mi][ni][1]);
            u1[p0] = tf32r(acc[mi][ni][2]);
            u1[p1] = tf32r(acc[mi][ni][3]);
        }
    }
}

// ======================= gemmL: per-l 128x128x512 Gram (pure cp.async) =======================
__global__ void __launch_bounds__(256, 2)
gemmL_mma(int Lp, int stepIdx) {
    extern __shared__ char sm[];
    unsigned sb = (unsigned)__cvta_generic_to_shared(sm);
    int tid = threadIdx.x, wid = tid >> 5, lid = tid & 31;
    int wr = wid & 3, wc = wid >> 2, gid = lid >> 2, tig = lid & 3;
    int l = blockIdx.x;

    int crow = tid >> 3, cc4 = tid & 7;
    int cpos = ((cc4 ^ ((crow & 3) << 1)) << 4);   // swizzled chunk byte offset
    unsigned abase[4], bbase[4];
#pragma unroll
    for (int j = 0; j < 4; j++) {
        int row = crow + j * 32;
        abase[j] = (unsigned)(row * Lp + l) * CC;
        bbase[j] = (unsigned)(row * LFULL + l) * CC;
    }

    // prologue: stages 0,1
#pragma unroll
    for (int ps = 0; ps < 2; ps++) {
        int kt = ps * KS;
        unsigned ab = sb + OFF_A(ps), bb = sb + OFF_B(ps);
#pragma unroll
        for (int j = 0; j < 4; j++) {
            int row = crow + j * 32;
            cp16(ab + row * ROWB + cpos, g_U + abase[j] + kt + cc4 * 4);
            cp16(bb + row * ROWB + cpos, g_P + bbase[j] + kt + cc4 * 4);
        }
        CP_COMMIT();
    }

    float acc[2][8][4] = {};
#pragma unroll 1
    for (int s = 0; s < 16; s++) {
        if (s < 15) CP_WAIT(1); else CP_WAIT(0);
        __syncthreads();
        if (s + 2 < 16) {
            int kt = (s + 2) * KS;
            int nb = (s + 2) % 3;
            unsigned ab = sb + OFF_A(nb), bb = sb + OFF_B(nb);
#pragma unroll
            for (int j = 0; j < 4; j++) {
                int row = crow + j * 32;
                cp16(ab + row * ROWB + cpos, g_U + abase[j] + kt + cc4 * 4);
                cp16(bb + row * ROWB + cpos, g_P + bbase[j] + kt + cc4 * 4);
            }
            CP_COMMIT();
        }
        int buf = s % 3;
        compute_half(sm, buf, 0, wr, wc, gid, tig, acc);
        compute_half(sm, buf, 1, wr, wc, gid, tig, acc);
    }
    __syncthreads();   // all compute done before S overwrites buffer 0

    // epilogue: S[n][m] = (acc + tb[n]) * INV_T
    float* S = (float*)sm;
#pragma unroll
    for (int mi = 0; mi < 2; mi++) {
        int n0 = wr * 32 + mi * 16 + gid;
        float tbl = g_tb[l * NN + n0];
        float tbh = g_tb[l * NN + n0 + 8];
#pragma unroll
        for (int ni = 0; ni < 8; ni++) {
            int col = wc * 64 + ni * 8 + 2 * tig;
            S[n0 * SPAD + col]           = (acc[mi][ni][0] + tbl) * INV_T;
            S[n0 * SPAD + col + 1]       = (acc[mi][ni][1] + tbl) * INV_T;
            S[(n0 + 8) * SPAD + col]     = (acc[mi][ni][2] + tbh) * INV_T;
            S[(n0 + 8) * SPAD + col + 1] = (acc[mi][ni][3] + tbh) * INV_T;
        }
    }
    __syncthreads();

    // NCE accuracy (INV_T > 0 preserves ordering)
    if (tid < 128) {
        float pos = S[tid * SPAD + tid];
        bool ok = true;
#pragma unroll 8
        for (int m = 0; m < NN; m++)
            ok = ok && ((m == tid) || (pos > S[tid * SPAD + m]));
        unsigned msk = __ballot_sync(0xffffffffu, ok);
        if (lid == 0) atomicAdd(&g_cnt[stepIdx], (unsigned)__popc(msk));
    }
    // coalesced staged store: S[n][m] -> g_tmp[l][n][m]
    for (int idx = tid; idx < NN * NN / 4; idx += 256) {
        int n2 = idx >> 5, m4 = (idx & 31) * 4;
        float4 v = *(float4*)&S[n2 * SPAD + m4];
        *(float4*)&g_tmp[((size_t)l * NN + n2) * NN + m4] = v;
    }
}

// ======================= launch =======================
extern "C" void kernel_launch(void* const* d_in, const int* in_sizes, int n_in,
                              void* d_out, int out_size) {
    const float* ts  = (const float*)d_in[0];
    const float* pts = (const float*)d_in[1];
    const float* W1  = (const float*)d_in[2];
    const float* b1  = (const float*)d_in[3];
    const float* W2  = (const float*)d_in[4];
    const float* b2  = (const float*)d_in[5];
    float* out = (float*)d_out;

    static bool attr_done = false;
    if (!attr_done) {
        cudaFuncSetAttribute(gemmU_mma, cudaFuncAttributeMaxDynamicSharedMemorySize, SM_TOTAL);
        cudaFuncSetAttribute(gemmL_mma, cudaFuncAttributeMaxDynamicSharedMemorySize, SM_TOTAL);
        attr_done = true;
    }

    init_kernel<<<1, 1>>>();
    // one-time: rounded + pair-permuted copies of T and P (reused by both steps)
    prepT_kernel<<<(NN * LFULL * CC / 32) / 256, 256>>>(ts);
    prepP_kernel<<<(NN * LFULL * CC / 32) / 256, 256>>>(pts);

    const float* Ws[2] = {W1, W2};
    const float* bs[2] = {b1, b2};
    int kb = 0;
    for (int si = 0; si < 2; si++) {
        int step = si + 1;
        int Lp = LFULL - step;
        wt_kernel<<<dim3(16, 16), dim3(32, 8)>>>(Ws[si]);
        tb_kernel<<<Lp, 128>>>(ts, bs[si], Lp, step);
        gemmU_mma<<<dim3(4, Lp), 256, SM_TOTAL>>>(Lp, step);
        gemmL_mma<<<Lp, 256, SM_TOTAL>>>(Lp, si);
        transpose_kernel<<<dim3(32, 4, 128), dim3(32, 8)>>>(out, Lp, kb);
        kb += Lp;
    }
    ytrue_kernel<<<(NN * KTOT + 255) / 256, 256>>>(out);
    acc_kernel<<<1, 1>>>(out);
}